// round 4
// baseline (speedup 1.0000x reference)
#include <cuda_runtime.h>
#include <cuda_bf16.h>

// out[b, de] = sum_k w[b,k] * A[k, de], with A diagonal (de % 257 == 0) zeroed.
// W: (2048, 32) f32   A: (32, 65536) f32   Out: (2048, 65536) f32
//
// FFMA2 (fma.rn.f32x2) register-tiled GEMM:
//   CTA tile: 256 de-cols x 256 batches (4 groups of 64)
//   Thread tile: 8 batches x 8 cols (4 f32x2 accumulators per batch row)
//   smem: As[32][256] (32KB, diag masked) + Ws[64][32] duplicated f32x2 (16KB) = 48KB static

#define KDIM 32
#define DE   65536
#define BN   256      // de columns per CTA
#define BM   64       // batches per group
#define NGRP 4        // groups per CTA (256 batches total)
#define NB   2048     // total batches

typedef unsigned long long ull;

__device__ __forceinline__ void ffma2(ull& d, ull a, ull b) {
    asm("fma.rn.f32x2 %0, %1, %2, %0;" : "+l"(d) : "l"(a), "l"(b));
}

__device__ __forceinline__ ull dup_f32(float v) {
    ull r;
    asm("mov.b64 %0, {%1, %1};" : "=l"(r) : "f"(v));
    return r;
}

__global__ __launch_bounds__(256, 2)
void explainer_kernel(const float* __restrict__ w,
                      const float* __restrict__ A,
                      float* __restrict__ out) {
    __shared__ __align__(16) float As[KDIM * BN];  // 32 KB
    __shared__ __align__(16) ull   Ws[BM * KDIM];  // 16 KB (each entry = (w,w) packed)

    const int tid   = threadIdx.x;
    const int cbase = blockIdx.x * BN;            // de offset of this CTA
    const int b0    = blockIdx.y * (BM * NGRP);   // first batch of this CTA

    // ---- Load A tile into smem, masking the diagonal (de == d*257) ----
    // 32 k x 256 floats = 2048 float4; 256 threads -> 8 float4 each, coalesced.
    #pragma unroll
    for (int i = 0; i < 8; i++) {
        int idx4 = tid + i * 256;            // float4 index within tile
        int k = idx4 >> 6;                   // idx4*4 / 256
        int j = (idx4 & 63) << 2;            // (idx4*4) % 256
        float4 v = *(const float4*)&A[k * DE + cbase + j];
        int de = cbase + j;
        if (((de + 0) % 257) == 0) v.x = 0.0f;
        if (((de + 1) % 257) == 0) v.y = 0.0f;
        if (((de + 2) % 257) == 0) v.z = 0.0f;
        if (((de + 3) % 257) == 0) v.w = 0.0f;
        *(float4*)&As[idx4 << 2] = v;
    }

    const int rb = tid >> 5;   // warp id 0..7 -> batch rows rb*8 .. rb*8+7
    const int cb = tid & 31;   // lane -> cols [cb*4, cb*4+4) and [128+cb*4, ...)

    #pragma unroll 1
    for (int g = 0; g < NGRP; g++) {
        if (g) __syncthreads();  // previous group done reading Ws

        // ---- Load 64x32 weights, duplicated into f32x2 (broadcast-ready) ----
        #pragma unroll
        for (int i = 0; i < 8; i++) {
            int idx = tid + i * 256;         // 0..2047
            // idx -> (row = idx/32, k = idx%32); global read is coalesced
            float wv = w[(b0 + g * BM) * KDIM + idx];
            Ws[idx] = dup_f32(wv);
        }
        __syncthreads();

        // ---- Main loop: 8 batches x 8 cols per thread ----
        ull acc[8][4];
        #pragma unroll
        for (int u = 0; u < 8; u++)
            #pragma unroll
            for (int j = 0; j < 4; j++)
                acc[u][j] = 0ull;

        #pragma unroll
        for (int k = 0; k < KDIM; k++) {
            // Two conflict-free LDS.128 (lanes stride 16B, contiguous 512B)
            ulonglong2 a0 = *(const ulonglong2*)&As[k * BN + (cb << 2)];
            ulonglong2 a1 = *(const ulonglong2*)&As[k * BN + 128 + (cb << 2)];
            #pragma unroll
            for (int u = 0; u < 8; u++) {
                ull wv = Ws[((rb << 3) + u) * KDIM + k];  // broadcast LDS.64
                ffma2(acc[u][0], a0.x, wv);
                ffma2(acc[u][1], a0.y, wv);
                ffma2(acc[u][2], a1.x, wv);
                ffma2(acc[u][3], a1.y, wv);
            }
        }

        // ---- Store: two float4 per batch row, streaming (skip L2 pollution) ----
        #pragma unroll
        for (int u = 0; u < 8; u++) {
            size_t row = (size_t)(b0 + g * BM + (rb << 3) + u);
            float* o = out + row * (size_t)DE + cbase;
            union { ull u2[2]; float4 f; } p0, p1;
            p0.u2[0] = acc[u][0]; p0.u2[1] = acc[u][1];
            p1.u2[0] = acc[u][2]; p1.u2[1] = acc[u][3];
            __stcs((float4*)&o[cb << 2], p0.f);
            __stcs((float4*)&o[128 + (cb << 2)], p1.f);
        }
    }
}

extern "C" void kernel_launch(void* const* d_in, const int* in_sizes, int n_in,
                              void* d_out, int out_size) {
    const float* w = (const float*)d_in[0];   // batch_weights (2048, 32)
    const float* A = (const float*)d_in[1];   // archs (32, 256, 256)
    float* out = (float*)d_out;               // (2048, 256, 256) f32

    dim3 grid(DE / BN, NB / (BM * NGRP));     // (256, 8)
    explainer_kernel<<<grid, 256>>>(w, A, out);
}

// round 5
// speedup vs baseline: 1.0013x; 1.0013x over previous
#include <cuda_runtime.h>
#include <cuda_bf16.h>

// out[b, de] = sum_k w[b,k] * A[k, de], A diagonal (de % 257 == 0) zeroed.
// W: (2048, 32) f32   A: (32, 65536) f32   Out: (2048, 65536) f32
//
// FFMA2 register-tiled GEMM, crossbar-optimized:
//   CTA tile: 256 de-cols x 256 batches (4 groups of 64)
//   Thread tile: 8 batches x 8 cols (4 f32x2 accumulators per batch row)
//   Weights packed 2-k-per-16B-broadcast: 1 LDS.128 wavefront feeds 8 FFMA2.
//   smem: As[32][256] (32KB) + Ws2[64][16] ulonglong2 (16KB) = 48KB static

#define KDIM 32
#define DE   65536
#define BN   256      // de columns per CTA
#define BM   64       // batches per group
#define NGRP 4        // groups per CTA (256 batches)
#define NB   2048

typedef unsigned long long ull;

__device__ __forceinline__ void ffma2(ull& d, ull a, ull b) {
    asm("fma.rn.f32x2 %0, %1, %2, %0;" : "+l"(d) : "l"(a), "l"(b));
}

__device__ __forceinline__ ull dup_f32(float v) {
    ull r;
    asm("mov.b64 %0, {%1, %1};" : "=l"(r) : "f"(v));
    return r;
}

__global__ __launch_bounds__(256, 2)
void explainer_kernel(const float* __restrict__ w,
                      const float* __restrict__ A,
                      float* __restrict__ out) {
    __shared__ __align__(16) float      As[KDIM * BN];        // 32 KB
    __shared__ __align__(16) ulonglong2 Ws2[BM * (KDIM / 2)]; // 16 KB

    const int tid   = threadIdx.x;
    const int cbase = blockIdx.x * BN;
    const int bblk  = blockIdx.y * (BM * NGRP);

    // ---- Load A tile into smem, masking the diagonal (de == d*257) ----
    #pragma unroll
    for (int i = 0; i < 8; i++) {
        int idx4 = tid + i * 256;            // float4 index within tile
        int k = idx4 >> 6;
        int j = (idx4 & 63) << 2;
        float4 v = *(const float4*)&A[k * DE + cbase + j];
        int de = cbase + j;
        if (((de + 0) % 257) == 0) v.x = 0.0f;
        if (((de + 1) % 257) == 0) v.y = 0.0f;
        if (((de + 2) % 257) == 0) v.z = 0.0f;
        if (((de + 3) % 257) == 0) v.w = 0.0f;
        *(float4*)&As[idx4 << 2] = v;
    }

    const int rb = tid >> 5;   // warp id 0..7 -> batch rows rb*8 .. rb*8+7
    const int cb = tid & 31;   // lane -> cols [cb*4, cb*4+4) and [128 + cb*4, ...)

    #pragma unroll 1
    for (int g = 0; g < NGRP; g++) {
        if (g) __syncthreads();  // previous group done reading Ws2

        // ---- Load 64x32 weights, packed as {w2k, w2k, w2k+1, w2k+1} ----
        // 64 rows x 16 kk-pairs = 1024 entries; 256 threads -> 4 each.
        #pragma unroll
        for (int i = 0; i < 4; i++) {
            int idx = tid + i * 256;          // 0..1023
            int row = idx >> 4;               // 0..63
            int kk  = idx & 15;               // 0..15
            float2 wv = *(const float2*)&w[(bblk + g * BM + row) * KDIM + (kk << 1)];
            ulonglong2 p;
            p.x = dup_f32(wv.x);
            p.y = dup_f32(wv.y);
            Ws2[idx] = p;
        }
        __syncthreads();

        ull acc[8][4];
        #pragma unroll
        for (int u = 0; u < 8; u++)
            #pragma unroll
            for (int j = 0; j < 4; j++)
                acc[u][j] = 0ull;

        // ---- Main loop: 16 kk iterations, 2 k-steps each ----
        #pragma unroll
        for (int kk = 0; kk < KDIM / 2; kk++) {
            ulonglong2 a0 = *(const ulonglong2*)&As[(2 * kk) * BN + (cb << 2)];
            ulonglong2 a1 = *(const ulonglong2*)&As[(2 * kk) * BN + 128 + (cb << 2)];
            ulonglong2 b0 = *(const ulonglong2*)&As[(2 * kk + 1) * BN + (cb << 2)];
            ulonglong2 b1 = *(const ulonglong2*)&As[(2 * kk + 1) * BN + 128 + (cb << 2)];
            #pragma unroll
            for (int u = 0; u < 8; u++) {
                ulonglong2 wp = Ws2[((rb << 3) + u) * (KDIM / 2) + kk]; // broadcast LDS.128
                ffma2(acc[u][0], a0.x, wp.x);
                ffma2(acc[u][1], a0.y, wp.x);
                ffma2(acc[u][2], a1.x, wp.x);
                ffma2(acc[u][3], a1.y, wp.x);
                ffma2(acc[u][0], b0.x, wp.y);
                ffma2(acc[u][1], b0.y, wp.y);
                ffma2(acc[u][2], b1.x, wp.y);
                ffma2(acc[u][3], b1.y, wp.y);
            }
        }

        // ---- Store: two float4 per batch row, streaming ----
        #pragma unroll
        for (int u = 0; u < 8; u++) {
            size_t row = (size_t)(bblk + g * BM + (rb << 3) + u);
            float* o = out + row * (size_t)DE + cbase;
            union { ull u2[2]; float4 f; } p0, p1;
            p0.u2[0] = acc[u][0]; p0.u2[1] = acc[u][1];
            p1.u2[0] = acc[u][2]; p1.u2[1] = acc[u][3];
            __stcs((float4*)&o[cb << 2], p0.f);
            __stcs((float4*)&o[128 + (cb << 2)], p1.f);
        }
    }
}

extern "C" void kernel_launch(void* const* d_in, const int* in_sizes, int n_in,
                              void* d_out, int out_size) {
    const float* w = (const float*)d_in[0];   // batch_weights (2048, 32)
    const float* A = (const float*)d_in[1];   // archs (32, 256, 256)
    float* out = (float*)d_out;               // (2048, 256, 256) f32

    dim3 grid(DE / BN, NB / (BM * NGRP));     // (256, 8)
    explainer_kernel<<<grid, 256>>>(w, A, out);
}

// round 7
// speedup vs baseline: 1.7335x; 1.7313x over previous
#include <cuda_runtime.h>
#include <cuda_bf16.h>
#include <cstdint>

// out[b, de] = sum_k w[b,k] * A[k, de], A diagonal (de % 257 == 0) zeroed for all k.
// W: (2048, 32) f32   A: (32, 65536) f32   Out: (2048, 65536) f32
//
// mma.sync.m16n8k16 bf16 GEMM with Karatsuba fp32 split (AhWh + AlWh + AhWl):
//   M = batch, N = de, K = 32 (2 k16 steps).
//   CTA: 256 batch x 128 de.  Warp: 32 batch (2 m16 groups) x 128 de (16 n8 frags).
//   W fragments in registers (hi/lo bf16), A-tile in smem packed as k-pair bf16x2
//   with row stride 20 words -> conflict-free LDS.32 b-fragment loads.
//   Dropped Al*Wl term ~2^-16 relative, far under the 1e-3 tolerance.

#define DE   65536
#define KD   32
#define TDE  128     // de per CTA
#define TB   256     // batch per CTA
#define NB   2048
#define ASTRIDE 20   // uint32 row stride for smem A tiles (conflict-free)

static __device__ __forceinline__ uint32_t pack_bf16x2(float lo_elem, float hi_elem) {
    // element0 (lower 16 bits) = first k (even), element1 = second k (odd)
    __nv_bfloat16 a = __float2bfloat16(lo_elem);
    __nv_bfloat16 b = __float2bfloat16(hi_elem);
    return (uint32_t)__bfloat16_as_ushort(a) | ((uint32_t)__bfloat16_as_ushort(b) << 16);
}

static __device__ __forceinline__ void mma16816(float* d, const uint32_t* a,
                                                uint32_t b0, uint32_t b1) {
    asm volatile(
        "mma.sync.aligned.m16n8k16.row.col.f32.bf16.bf16.f32 "
        "{%0,%1,%2,%3}, {%4,%5,%6,%7}, {%8,%9}, {%0,%1,%2,%3};"
        : "+f"(d[0]), "+f"(d[1]), "+f"(d[2]), "+f"(d[3])
        : "r"(a[0]), "r"(a[1]), "r"(a[2]), "r"(a[3]), "r"(b0), "r"(b1));
}

__global__ __launch_bounds__(256)
void explainer_hmma(const float* __restrict__ w,
                    const float* __restrict__ A,
                    float* __restrict__ out) {
    __shared__ uint32_t Ah[TDE * ASTRIDE];  // 10240 B
    __shared__ uint32_t Al[TDE * ASTRIDE];  // 10240 B

    const int tid = threadIdx.x;
    const int de0 = blockIdx.x * TDE;
    const int b0  = blockIdx.y * TB;

    // ---- Load A tile: 128 de x 16 k-pairs; split hi/lo bf16, pack per k-pair ----
    // Per warp-instruction: fixed pair p, 32 consecutive de -> coalesced 128B LDG.
    #pragma unroll
    for (int i = 0; i < 8; i++) {
        int idx = tid + i * 256;        // 0..2047
        int p   = idx >> 7;             // k-pair 0..15 (k = 2p, 2p+1)
        int de  = idx & 127;
        int k0  = p << 1;
        float v0 = A[(size_t)k0 * DE + de0 + de];
        float v1 = A[(size_t)(k0 + 1) * DE + de0 + de];
        if (((de0 + de) % 257) == 0) { v0 = 0.0f; v1 = 0.0f; }
        float h0 = __bfloat162float(__float2bfloat16(v0));
        float h1 = __bfloat162float(__float2bfloat16(v1));
        Ah[de * ASTRIDE + p] = pack_bf16x2(h0, h1);
        Al[de * ASTRIDE + p] = pack_bf16x2(v0 - h0, v1 - h1);
    }

    // ---- W fragments in registers: warp covers 32 batches (2 m16 groups) ----
    const int warp = tid >> 5;
    const int lane = tid & 31;
    const int qr = lane >> 2;   // 0..7  (row within m16 group / n col within n8)
    const int qc = lane & 3;    // 0..3  (k-pair lane)
    const int mb = b0 + warp * 32;

    uint32_t whi[2][2][4], wlo[2][2][4];   // [m-group][k-step][a-reg]
    #pragma unroll
    for (int g = 0; g < 2; g++) {
        #pragma unroll
        for (int s = 0; s < 2; s++) {
            #pragma unroll
            for (int h = 0; h < 2; h++) {        // k-half: +0 / +8
                #pragma unroll
                for (int rr = 0; rr < 2; rr++) { // row: +0 / +8
                    int row = mb + g * 16 + qr + rr * 8;
                    int kk  = s * 16 + 2 * qc + h * 8;
                    float2 v = *(const float2*)&w[(size_t)row * KD + kk];
                    float hx = __bfloat162float(__float2bfloat16(v.x));
                    float hy = __bfloat162float(__float2bfloat16(v.y));
                    int reg = rr + 2 * h;  // {a0a1, a2a3, a4a5, a6a7}
                    whi[g][s][reg] = pack_bf16x2(hx, hy);
                    wlo[g][s][reg] = pack_bf16x2(v.x - hx, v.y - hy);
                }
            }
        }
    }
    __syncthreads();

    // ---- Main loop: 16 n8 fragments of de ----
    #pragma unroll 4
    for (int f = 0; f < 16; f++) {
        const uint32_t* ar = &Ah[(f * 8 + qr) * ASTRIDE];  // b-frag n col = qr
        const uint32_t* al = &Al[(f * 8 + qr) * ASTRIDE];
        // k-step s: b0b1 at pair (8s + qc), b2b3 at pair (8s + qc + 4)
        uint32_t bh00 = ar[qc],     bh01 = ar[qc + 4];
        uint32_t bh10 = ar[8 + qc], bh11 = ar[12 + qc];
        uint32_t bl00 = al[qc],     bl01 = al[qc + 4];
        uint32_t bl10 = al[8 + qc], bl11 = al[12 + qc];

        float d[2][4] = {{0.f, 0.f, 0.f, 0.f}, {0.f, 0.f, 0.f, 0.f}};
        #pragma unroll
        for (int g = 0; g < 2; g++) {
            mma16816(d[g], whi[g][0], bh00, bh01);   // Wh*Ah (k-step 0)
            mma16816(d[g], whi[g][1], bh10, bh11);   // Wh*Ah (k-step 1)
            mma16816(d[g], wlo[g][0], bh00, bh01);   // Wl*Ah
            mma16816(d[g], wlo[g][1], bh10, bh11);
            mma16816(d[g], whi[g][0], bl00, bl01);   // Wh*Al
            mma16816(d[g], whi[g][1], bl10, bl11);
        }

        // ---- Store: d0,d1 = (row, col), (row, col+1); d2,d3 = row+8 ----
        int col = de0 + f * 8 + 2 * qc;
        #pragma unroll
        for (int g = 0; g < 2; g++) {
            size_t row = (size_t)(mb + g * 16 + qr);
            float2 p0 = make_float2(d[g][0], d[g][1]);
            float2 p1 = make_float2(d[g][2], d[g][3]);
            __stcs((float2*)&out[row * DE + col], p0);
            __stcs((float2*)&out[(row + 8) * DE + col], p1);
        }
    }
}

extern "C" void kernel_launch(void* const* d_in, const int* in_sizes, int n_in,
                              void* d_out, int out_size) {
    const float* w = (const float*)d_in[0];   // batch_weights (2048, 32)
    const float* A = (const float*)d_in[1];   // archs (32, 256, 256)
    float* out = (float*)d_out;               // (2048, 256, 256) f32

    dim3 grid(DE / TDE, NB / TB);             // (512, 8)
    explainer_hmma<<<grid, 256>>>(w, A, out);
}

// round 8
// speedup vs baseline: 1.8277x; 1.0544x over previous
#include <cuda_runtime.h>
#include <cuda_bf16.h>
#include <cstdint>

// out[b, de] = sum_k w[b,k] * A[k, de], A diagonal (de % 257 == 0) zeroed for all k.
// W: (2048, 32) f32   A: (32, 65536) f32   Out: (2048, 65536) f32
//
// mma.sync.m16n8k16 bf16 Karatsuba GEMM (AhWh + AlWh + AhWl) with a staged,
// fully-coalesced epilogue:
//   CTA: 256 batch x 128 de.  Warp: 32 batch x 128 de (16 n8 frags, 4 chunks of 4).
//   Per chunk: compute 32 de worth of accumulators, stage to per-warp smem
//   (stride 40 floats -> conflict-free STS.64 and LDS.128), then STG.128 full
//   128B lines (4 lines/instr, 4 sectors each) instead of 8 fragmented lines.

#define DE   65536
#define KD   32
#define TDE  128     // de per CTA
#define TB   256     // batch per CTA
#define NB   2048
#define ASTRIDE 20   // uint32 row stride for A tiles (conflict-free LDS.32)
#define SSTRIDE 40   // float row stride for staging (conflict-free STS.64/LDS.128)

// dynamic smem layout (bytes)
#define SM_AH    0
#define SM_AL    (TDE * ASTRIDE * 4)              // 10240
#define SM_STAGE (2 * TDE * ASTRIDE * 4)          // 20480
#define SM_TOTAL (SM_STAGE + 8 * 32 * SSTRIDE * 4)  // 61440

static __device__ __forceinline__ uint32_t pack_bf16x2(float e0, float e1) {
    __nv_bfloat16 a = __float2bfloat16(e0);
    __nv_bfloat16 b = __float2bfloat16(e1);
    return (uint32_t)__bfloat16_as_ushort(a) | ((uint32_t)__bfloat16_as_ushort(b) << 16);
}

static __device__ __forceinline__ void mma16816(float* d, const uint32_t* a,
                                                uint32_t b0, uint32_t b1) {
    asm volatile(
        "mma.sync.aligned.m16n8k16.row.col.f32.bf16.bf16.f32 "
        "{%0,%1,%2,%3}, {%4,%5,%6,%7}, {%8,%9}, {%0,%1,%2,%3};"
        : "+f"(d[0]), "+f"(d[1]), "+f"(d[2]), "+f"(d[3])
        : "r"(a[0]), "r"(a[1]), "r"(a[2]), "r"(a[3]), "r"(b0), "r"(b1));
}

__global__ __launch_bounds__(256, 2)
void explainer_hmma(const float* __restrict__ w,
                    const float* __restrict__ A,
                    float* __restrict__ out) {
    extern __shared__ char smem[];
    uint32_t* Ah = (uint32_t*)(smem + SM_AH);
    uint32_t* Al = (uint32_t*)(smem + SM_AL);

    const int tid = threadIdx.x;
    const int de0 = blockIdx.x * TDE;
    const int b0  = blockIdx.y * TB;

    // ---- Load A tile: 128 de x 16 k-pairs; split hi/lo bf16 ----
    #pragma unroll
    for (int i = 0; i < 8; i++) {
        int idx = tid + i * 256;        // 0..2047
        int p   = idx >> 7;             // k-pair 0..15
        int de  = idx & 127;
        int k0  = p << 1;
        float v0 = A[(size_t)k0 * DE + de0 + de];
        float v1 = A[(size_t)(k0 + 1) * DE + de0 + de];
        if (((de0 + de) % 257) == 0) { v0 = 0.0f; v1 = 0.0f; }
        float h0 = __bfloat162float(__float2bfloat16(v0));
        float h1 = __bfloat162float(__float2bfloat16(v1));
        Ah[de * ASTRIDE + p] = pack_bf16x2(h0, h1);
        Al[de * ASTRIDE + p] = pack_bf16x2(v0 - h0, v1 - h1);
    }

    // ---- W fragments in registers: warp covers 32 batches (2 m16 groups) ----
    const int warp = tid >> 5;
    const int lane = tid & 31;
    const int qr = lane >> 2;   // 0..7
    const int qc = lane & 3;    // 0..3
    const int mb = b0 + warp * 32;

    uint32_t whi[2][2][4], wlo[2][2][4];   // [m-group][k-step][a-reg]
    #pragma unroll
    for (int g = 0; g < 2; g++) {
        #pragma unroll
        for (int s = 0; s < 2; s++) {
            #pragma unroll
            for (int h = 0; h < 2; h++) {
                #pragma unroll
                for (int rr = 0; rr < 2; rr++) {
                    int row = mb + g * 16 + qr + rr * 8;
                    int kk  = s * 16 + 2 * qc + h * 8;
                    float2 v = *(const float2*)&w[(size_t)row * KD + kk];
                    float hx = __bfloat162float(__float2bfloat16(v.x));
                    float hy = __bfloat162float(__float2bfloat16(v.y));
                    int reg = rr + 2 * h;
                    whi[g][s][reg] = pack_bf16x2(hx, hy);
                    wlo[g][s][reg] = pack_bf16x2(v.x - hx, v.y - hy);
                }
            }
        }
    }
    __syncthreads();

    float* Sw = (float*)(smem + SM_STAGE) + warp * 32 * SSTRIDE;
    const int rsub = lane >> 3;   // 0..3  (row within 4-row store group)
    const int c8   = lane & 7;    // 0..7  (float4 column)

    // ---- 4 chunks of 4 n8-fragments (32 consecutive de per chunk) ----
    #pragma unroll 1
    for (int c = 0; c < 4; c++) {
        float dd[4][2][4];

        #pragma unroll
        for (int f = 0; f < 4; f++) {
            int fc = c * 4 + f;
            const uint32_t* ar = &Ah[(fc * 8 + qr) * ASTRIDE];
            const uint32_t* al = &Al[(fc * 8 + qr) * ASTRIDE];
            uint32_t bh00 = ar[qc],     bh01 = ar[qc + 4];
            uint32_t bh10 = ar[8 + qc], bh11 = ar[12 + qc];
            uint32_t bl00 = al[qc],     bl01 = al[qc + 4];
            uint32_t bl10 = al[8 + qc], bl11 = al[12 + qc];

            #pragma unroll
            for (int g = 0; g < 2; g++) {
                dd[f][g][0] = 0.f; dd[f][g][1] = 0.f;
                dd[f][g][2] = 0.f; dd[f][g][3] = 0.f;
                mma16816(dd[f][g], whi[g][0], bh00, bh01);
                mma16816(dd[f][g], whi[g][1], bh10, bh11);
                mma16816(dd[f][g], wlo[g][0], bh00, bh01);
                mma16816(dd[f][g], wlo[g][1], bh10, bh11);
                mma16816(dd[f][g], whi[g][0], bl00, bl01);
                mma16816(dd[f][g], whi[g][1], bl10, bl11);
            }
        }

        // ---- Stage: STS.64, stride 40 -> conflict-free per half-warp phase ----
        #pragma unroll
        for (int f = 0; f < 4; f++) {
            int colf = f * 8 + 2 * qc;
            #pragma unroll
            for (int g = 0; g < 2; g++) {
                *(float2*)&Sw[(g * 16 + qr) * SSTRIDE + colf] =
                    make_float2(dd[f][g][0], dd[f][g][1]);
                *(float2*)&Sw[(g * 16 + qr + 8) * SSTRIDE + colf] =
                    make_float2(dd[f][g][2], dd[f][g][3]);
            }
        }
        __syncwarp();

        // ---- Drain: LDS.128 (conflict-free) + fully-coalesced STG.128 ----
        #pragma unroll
        for (int i = 0; i < 8; i++) {
            int r = i * 4 + rsub;
            float4 v = *(const float4*)&Sw[r * SSTRIDE + c8 * 4];
            __stcs((float4*)&out[(size_t)(mb + r) * DE + de0 + c * 32 + c8 * 4], v);
        }
        __syncwarp();
    }
}

extern "C" void kernel_launch(void* const* d_in, const int* in_sizes, int n_in,
                              void* d_out, int out_size) {
    const float* w = (const float*)d_in[0];   // batch_weights (2048, 32)
    const float* A = (const float*)d_in[1];   // archs (32, 256, 256)
    float* out = (float*)d_out;               // (2048, 256, 256) f32

    cudaFuncSetAttribute(explainer_hmma, cudaFuncAttributeMaxDynamicSharedMemorySize,
                         SM_TOTAL);
    dim3 grid(DE / TDE, NB / TB);             // (512, 8)
    explainer_hmma<<<grid, 256, SM_TOTAL>>>(w, A, out);
}